// round 2
// baseline (speedup 1.0000x reference)
#include <cuda_runtime.h>
#include <math.h>

// Problem constants
constexpr int Bb = 8;
constexpr int Cc = 512;
constexpr int Ss = 1024;     // H*W
constexpr int M3 = 1536;     // 3*C
constexpr int NH = 8;
constexpr int HD = 64;

// Scratch buffers (static device globals; allocation is forbidden)
__device__ float g_h[Bb * Cc * Ss];      // groupnorm output, [b][c][s]
__device__ float g_qkv[Bb * M3 * Ss];    // qkv, [b][o][s]
__device__ float g_hf[Bb * Ss * Cc];     // attn out / INL ping, [b*s][c]
__device__ float g_hf2[Bb * Ss * Cc];    // INL pong

// ---------------------------------------------------------------------------
// GroupNorm: one block per (b, group). 64 channels x 1024 spatial per group.
// ---------------------------------------------------------------------------
__global__ void gn_kernel(const float* __restrict__ x,
                          const float* __restrict__ scale,
                          const float* __restrict__ bias) {
    const int b = blockIdx.x >> 3;
    const int g = blockIdx.x & 7;
    const int N = 64 * Ss;  // 65536
    const size_t base = (size_t)b * Cc * Ss + (size_t)g * 64 * Ss;
    const float* xp = x + base;

    float s = 0.f, s2 = 0.f;
    for (int i = threadIdx.x; i < N; i += 256) {
        float v = xp[i];
        s += v; s2 += v * v;
    }
    __shared__ float rs[256], rs2[256];
    rs[threadIdx.x] = s; rs2[threadIdx.x] = s2;
    __syncthreads();
    for (int o = 128; o > 0; o >>= 1) {
        if (threadIdx.x < o) {
            rs[threadIdx.x] += rs[threadIdx.x + o];
            rs2[threadIdx.x] += rs2[threadIdx.x + o];
        }
        __syncthreads();
    }
    const float mean = rs[0] / N;
    float var = rs2[0] / N - mean * mean;
    var = fmaxf(var, 0.f);
    const float rstd = rsqrtf(var + 1e-5f);

    for (int i = threadIdx.x; i < N; i += 256) {
        int c = g * 64 + (i >> 10);
        g_h[base + i] = (xp[i] - mean) * rstd * scale[c] + bias[c];
    }
}

// ---------------------------------------------------------------------------
// QKV GEMM (NN): qkv[b,m,n] = sum_k W[m,k] * h[b,k,n] + bias[m]
// M=1536, K=512, N=1024. 64x64 tile, BK=16, 256 threads, 4x4 micro-tile.
// ---------------------------------------------------------------------------
__global__ void qkv_gemm(const float* __restrict__ W,
                         const float* __restrict__ bias) {
    __shared__ __align__(16) float As[16][64];
    __shared__ __align__(16) float Bs[16][64];
    const int b = blockIdx.z;
    const int n0 = blockIdx.x * 64;
    const int m0 = blockIdx.y * 64;
    const int tid = threadIdx.x;
    const int tx = tid & 15, ty = tid >> 4;

    const float* Bbase = g_h + (size_t)b * Cc * Ss;
    const int la_m = tid >> 2;
    const int la_k = (tid & 3) * 4;
    const int lb_k = tid >> 4;
    const int lb_n = (tid & 15) * 4;

    float acc[4][4] = {};

    for (int k0 = 0; k0 < Cc; k0 += 16) {
        float4 av = *(const float4*)(W + (size_t)(m0 + la_m) * Cc + k0 + la_k);
        As[la_k + 0][la_m] = av.x;
        As[la_k + 1][la_m] = av.y;
        As[la_k + 2][la_m] = av.z;
        As[la_k + 3][la_m] = av.w;
        *(float4*)&Bs[lb_k][lb_n] =
            *(const float4*)(Bbase + (size_t)(k0 + lb_k) * Ss + n0 + lb_n);
        __syncthreads();
#pragma unroll
        for (int kk = 0; kk < 16; kk++) {
            float a4[4], b4[4];
            *(float4*)a4 = *(const float4*)&As[kk][ty * 4];
            *(float4*)b4 = *(const float4*)&Bs[kk][tx * 4];
#pragma unroll
            for (int i = 0; i < 4; i++)
#pragma unroll
                for (int j = 0; j < 4; j++)
                    acc[i][j] += a4[i] * b4[j];
        }
        __syncthreads();
    }

    float* out = g_qkv + (size_t)b * M3 * Ss;
#pragma unroll
    for (int i = 0; i < 4; i++) {
        const int m = m0 + ty * 4 + i;
        const float bv = bias[m];
        float4 r = make_float4(acc[i][0] + bv, acc[i][1] + bv,
                               acc[i][2] + bv, acc[i][3] + bv);
        *(float4*)(out + (size_t)m * Ss + n0 + tx * 4) = r;
    }
}

// ---------------------------------------------------------------------------
// Attention (flash-style, fp32). One block per (b, head, s-tile of 64).
// 256 threads; each thread owns a 4x4 block of the 64x64 score tile
// (rows ty*4+i, cols tx*4+j) AND the same 4x4 block in (s,d) space for O.
// Softmax stats (m, l, corr) are thread-local, replicated across the 16
// lanes of each row group (reduced via shfl within the 16-lane half-warp).
// ---------------------------------------------------------------------------
__global__ void attn_kernel() {
    extern __shared__ float sm[];
    float* Qs = sm;                  // [64 d][64 s]
    float* Ks = Qs + 64 * 64;        // [64 d][64 t]
    float* Vst = Ks + 64 * 64;       // [64 t][65]  (t-major, padded)
    float* Ps = Vst + 64 * 65;       // [64 s][68]  (s-major, padded)

    const int tid = threadIdx.x;
    const int tx = tid & 15, ty = tid >> 4;
    const int b = blockIdx.y >> 3;
    const int hh = blockIdx.y & 7;
    const int s0 = blockIdx.x * 64;

    const float* qk = g_qkv + (size_t)b * M3 * Ss;
    const float* Qg = qk + (size_t)(hh * HD) * Ss + s0;
    const float* Kg = qk + (size_t)(Cc + hh * HD) * Ss;
    const float* Vg = qk + (size_t)(2 * Cc + hh * HD) * Ss;

    // Load Q tile [64 d][64 s], pre-scaled by hd^-0.5 = 0.125
#pragma unroll
    for (int r = 0; r < 16; r++) {
        int idx = r * 256 + tid;
        int d = idx >> 6, ss = idx & 63;
        Qs[idx] = Qg[(size_t)d * Ss + ss] * 0.125f;
    }

    float m_i[4], l_i[4];
#pragma unroll
    for (int i = 0; i < 4; i++) { m_i[i] = -1e30f; l_i[i] = 0.f; }
    float accO[4][4] = {};

    __syncthreads();

    for (int t0 = 0; t0 < Ss; t0 += 64) {
        // Load K tile [64 d][64 t] and V tile transposed [64 t][64 d]
#pragma unroll
        for (int r = 0; r < 16; r++) {
            int idx = r * 256 + tid;
            int d = idx >> 6, tt = idx & 63;
            float kv = Kg[(size_t)d * Ss + t0 + tt];
            float vv = Vg[(size_t)d * Ss + t0 + tt];
            Ks[idx] = kv;
            Vst[tt * 65 + d] = vv;
        }
        __syncthreads();

        // Score tile: sc[s][t] = sum_d Q[d][s]*K[d][t]  (rows ty*4+i, cols tx*4+j)
        float sc[4][4] = {};
#pragma unroll 8
        for (int kk = 0; kk < 64; kk++) {
            float a4[4], b4[4];
            *(float4*)a4 = *(const float4*)&Qs[kk * 64 + ty * 4];
            *(float4*)b4 = *(const float4*)&Ks[kk * 64 + tx * 4];
#pragma unroll
            for (int i = 0; i < 4; i++)
#pragma unroll
                for (int j = 0; j < 4; j++)
                    sc[i][j] += a4[i] * b4[j];
        }

        // Online softmax per s-row. The 16 lanes sharing a row group are
        // lanes 0..15 or 16..31 of a warp; shfl offsets 8..1 stay inside.
        float corr[4];
#pragma unroll
        for (int i = 0; i < 4; i++) {
            float tm = fmaxf(fmaxf(sc[i][0], sc[i][1]), fmaxf(sc[i][2], sc[i][3]));
#pragma unroll
            for (int off = 8; off >= 1; off >>= 1)
                tm = fmaxf(tm, __shfl_xor_sync(0xffffffffu, tm, off));
            const float nm = fmaxf(m_i[i], tm);
            corr[i] = __expf(m_i[i] - nm);
            float pv[4], ps = 0.f;
#pragma unroll
            for (int j = 0; j < 4; j++) { pv[j] = __expf(sc[i][j] - nm); ps += pv[j]; }
            *(float4*)&Ps[(ty * 4 + i) * 68 + tx * 4] =
                make_float4(pv[0], pv[1], pv[2], pv[3]);
#pragma unroll
            for (int off = 8; off >= 1; off >>= 1)
                ps += __shfl_xor_sync(0xffffffffu, ps, off);
            l_i[i] = l_i[i] * corr[i] + ps;
            m_i[i] = nm;
        }
        __syncthreads();

        // O accumulate: O[s][d] = O[s][d]*corr + sum_t P[s][t]*V[t][d]
        // Thread block in O space: rows ty*4+i, cols tx*4+j.
#pragma unroll
        for (int i = 0; i < 4; i++)
#pragma unroll
            for (int j = 0; j < 4; j++) accO[i][j] *= corr[i];

        const int d4 = tx * 4;
#pragma unroll 4
        for (int kk = 0; kk < 64; kk++) {
            const float v0 = Vst[kk * 65 + d4 + 0];
            const float v1 = Vst[kk * 65 + d4 + 1];
            const float v2 = Vst[kk * 65 + d4 + 2];
            const float v3 = Vst[kk * 65 + d4 + 3];
#pragma unroll
            for (int i = 0; i < 4; i++) {
                const float p = Ps[(ty * 4 + i) * 68 + kk];
                accO[i][0] += p * v0;
                accO[i][1] += p * v1;
                accO[i][2] += p * v2;
                accO[i][3] += p * v3;
            }
        }
        __syncthreads();
    }

    // Finalize: divide by l, write to hf[b*S+s][hh*64+d]
    float* out = g_hf + ((size_t)b * Ss + s0) * Cc + hh * HD;
#pragma unroll
    for (int i = 0; i < 4; i++) {
        const float inv = 1.f / l_i[i];
        float4 r = make_float4(accO[i][0] * inv, accO[i][1] * inv,
                               accO[i][2] * inv, accO[i][3] * inv);
        *(float4*)(out + (size_t)(ty * 4 + i) * Cc + tx * 4) = r;
    }
}

// ---------------------------------------------------------------------------
// INL step (NT GEMM + fused Euler/tanh epilogue):
// hout[r,o] = hin[r,o] + 0.1*tanh(sum_c hin[r,c]*W[o,c] + bias[o])
// ---------------------------------------------------------------------------
__global__ void inl_gemm(int src, const float* __restrict__ W,
                         const float* __restrict__ bias) {
    const float* hin = src ? g_hf2 : g_hf;
    float* hout = src ? g_hf : g_hf2;

    __shared__ __align__(16) float As[16][64];
    __shared__ __align__(16) float Ws[16][64];
    const int n0 = blockIdx.x * 64;
    const int m0 = blockIdx.y * 64;
    const int tid = threadIdx.x;
    const int tx = tid & 15, ty = tid >> 4;
    const int la_m = tid >> 2;
    const int la_k = (tid & 3) * 4;

    float acc[4][4] = {};

    for (int k0 = 0; k0 < Cc; k0 += 16) {
        float4 av = *(const float4*)(hin + (size_t)(m0 + la_m) * Cc + k0 + la_k);
        As[la_k + 0][la_m] = av.x;
        As[la_k + 1][la_m] = av.y;
        As[la_k + 2][la_m] = av.z;
        As[la_k + 3][la_m] = av.w;
        float4 wv = *(const float4*)(W + (size_t)(n0 + la_m) * Cc + k0 + la_k);
        Ws[la_k + 0][la_m] = wv.x;
        Ws[la_k + 1][la_m] = wv.y;
        Ws[la_k + 2][la_m] = wv.z;
        Ws[la_k + 3][la_m] = wv.w;
        __syncthreads();
#pragma unroll
        for (int kk = 0; kk < 16; kk++) {
            float a4[4], b4[4];
            *(float4*)a4 = *(const float4*)&As[kk][ty * 4];
            *(float4*)b4 = *(const float4*)&Ws[kk][tx * 4];
#pragma unroll
            for (int i = 0; i < 4; i++)
#pragma unroll
                for (int j = 0; j < 4; j++)
                    acc[i][j] += a4[i] * b4[j];
        }
        __syncthreads();
    }

#pragma unroll
    for (int i = 0; i < 4; i++) {
        const size_t row = m0 + ty * 4 + i;
        float4 prev = *(const float4*)(hin + row * Cc + n0 + tx * 4);
        float4 r;
        r.x = prev.x + 0.1f * tanhf(acc[i][0] + bias[n0 + tx * 4 + 0]);
        r.y = prev.y + 0.1f * tanhf(acc[i][1] + bias[n0 + tx * 4 + 1]);
        r.z = prev.z + 0.1f * tanhf(acc[i][2] + bias[n0 + tx * 4 + 2]);
        r.w = prev.w + 0.1f * tanhf(acc[i][3] + bias[n0 + tx * 4 + 3]);
        *(float4*)(hout + row * Cc + n0 + tx * 4) = r;
    }
}

// ---------------------------------------------------------------------------
// Proj (NT GEMM + fused residual, transposed write):
// out[b,o,s] = x[b,o,s] + sum_c hf2[b*S+s,c]*W[o,c] + bias[o]
// ---------------------------------------------------------------------------
__global__ void proj_gemm(const float* __restrict__ W,
                          const float* __restrict__ bias,
                          const float* __restrict__ x,
                          float* __restrict__ out) {
    const float* hin = g_hf2;

    __shared__ __align__(16) float As[16][64];
    __shared__ __align__(16) float Ws[16][64];
    const int n0 = blockIdx.x * 64;
    const int m0 = blockIdx.y * 64;
    const int tid = threadIdx.x;
    const int tx = tid & 15, ty = tid >> 4;
    const int la_m = tid >> 2;
    const int la_k = (tid & 3) * 4;

    float acc[4][4] = {};

    for (int k0 = 0; k0 < Cc; k0 += 16) {
        float4 av = *(const float4*)(hin + (size_t)(m0 + la_m) * Cc + k0 + la_k);
        As[la_k + 0][la_m] = av.x;
        As[la_k + 1][la_m] = av.y;
        As[la_k + 2][la_m] = av.z;
        As[la_k + 3][la_m] = av.w;
        float4 wv = *(const float4*)(W + (size_t)(n0 + la_m) * Cc + k0 + la_k);
        Ws[la_k + 0][la_m] = wv.x;
        Ws[la_k + 1][la_m] = wv.y;
        Ws[la_k + 2][la_m] = wv.z;
        Ws[la_k + 3][la_m] = wv.w;
        __syncthreads();
#pragma unroll
        for (int kk = 0; kk < 16; kk++) {
            float a4[4], b4[4];
            *(float4*)a4 = *(const float4*)&As[kk][ty * 4];
            *(float4*)b4 = *(const float4*)&Ws[kk][tx * 4];
#pragma unroll
            for (int i = 0; i < 4; i++)
#pragma unroll
                for (int j = 0; j < 4; j++)
                    acc[i][j] += a4[i] * b4[j];
        }
        __syncthreads();
    }

    // rows m0..m0+63 all lie in one batch (64 | 1024)
    const int b = m0 >> 10;
    const int s_base = (m0 & 1023) + ty * 4;
#pragma unroll
    for (int j = 0; j < 4; j++) {
        const int o = n0 + tx * 4 + j;
        const float bv = bias[o];
        const size_t idx = ((size_t)b * Cc + o) * Ss + s_base;
        float4 xv = *(const float4*)(x + idx);
        float4 r = make_float4(xv.x + acc[0][j] + bv, xv.y + acc[1][j] + bv,
                               xv.z + acc[2][j] + bv, xv.w + acc[3][j] + bv);
        *(float4*)(out + idx) = r;
    }
}

// ---------------------------------------------------------------------------
extern "C" void kernel_launch(void* const* d_in, const int* in_sizes, int n_in,
                              void* d_out, int out_size) {
    const float* x = (const float*)d_in[0];
    const float* gn_scale = (const float*)d_in[1];
    const float* gn_bias = (const float*)d_in[2];
    const float* qkv_w = (const float*)d_in[3];
    const float* qkv_b = (const float*)d_in[4];
    const float* proj_w = (const float*)d_in[5];
    const float* proj_b = (const float*)d_in[6];
    const float* inl_w = (const float*)d_in[7];
    const float* inl_b = (const float*)d_in[8];
    float* out = (float*)d_out;

    // 1. GroupNorm -> g_h
    gn_kernel<<<Bb * 8, 256>>>(x, gn_scale, gn_bias);

    // 2. QKV GEMM -> g_qkv
    qkv_gemm<<<dim3(Ss / 64, M3 / 64, Bb), 256>>>(qkv_w, qkv_b);

    // 3. Attention -> g_hf
    const int attn_smem =
        (64 * 64 + 64 * 64 + 64 * 65 + 64 * 68) * (int)sizeof(float);  // ~66.3 KB
    cudaFuncSetAttribute(attn_kernel,
                         cudaFuncAttributeMaxDynamicSharedMemorySize, attn_smem);
    attn_kernel<<<dim3(Ss / 64, Bb * NH), 256, attn_smem>>>();

    // 4. INL: 3 Euler steps (ping-pong g_hf <-> g_hf2), ends in g_hf2
    inl_gemm<<<dim3(Cc / 64, Bb * Ss / 64), 256>>>(0, inl_w, inl_b);
    inl_gemm<<<dim3(Cc / 64, Bb * Ss / 64), 256>>>(1, inl_w, inl_b);
    inl_gemm<<<dim3(Cc / 64, Bb * Ss / 64), 256>>>(0, inl_w, inl_b);

    // 5. Proj + residual -> d_out
    proj_gemm<<<dim3(Cc / 64, Bb * Ss / 64), 256>>>(proj_w, proj_b, x, out);
}

// round 4
// speedup vs baseline: 1.2644x; 1.2644x over previous
#include <cuda_runtime.h>
#include <math.h>

// Problem constants
constexpr int Bb = 8;
constexpr int Cc = 512;
constexpr int Ss = 1024;     // H*W
constexpr int M3 = 1536;     // 3*C
constexpr int NH = 8;
constexpr int HD = 64;

// Scratch buffers (static device globals; allocation is forbidden)
__device__ float g_h[Bb * Cc * Ss];      // groupnorm output, [b][c][s]
__device__ float g_qkv[Bb * M3 * Ss];    // qkv, [b][o][s]
__device__ float g_hf[Bb * Ss * Cc];     // attn out / INL ping, [b*s][c]
__device__ float g_hf2[Bb * Ss * Cc];    // INL pong

__device__ __forceinline__ float fast_tanh(float x) {
    x = fminf(fmaxf(x, -15.f), 15.f);
    float e = __expf(2.f * x);
    return __fdividef(e - 1.f, e + 1.f);
}

// ---------------------------------------------------------------------------
// GroupNorm: one block per (b, group). 64 channels x 1024 spatial per group.
// ---------------------------------------------------------------------------
__global__ void gn_kernel(const float* __restrict__ x,
                          const float* __restrict__ scale,
                          const float* __restrict__ bias) {
    const int b = blockIdx.x >> 3;
    const int g = blockIdx.x & 7;
    const int N = 64 * Ss;  // 65536
    const size_t base = (size_t)b * Cc * Ss + (size_t)g * 64 * Ss;
    const float* xp = x + base;

    float s = 0.f, s2 = 0.f;
    for (int i = threadIdx.x * 4; i < N; i += 1024) {
        float4 v = *(const float4*)(xp + i);
        s += v.x + v.y + v.z + v.w;
        s2 += v.x * v.x + v.y * v.y + v.z * v.z + v.w * v.w;
    }
    __shared__ float rs[256], rs2[256];
    rs[threadIdx.x] = s; rs2[threadIdx.x] = s2;
    __syncthreads();
    for (int o = 128; o > 0; o >>= 1) {
        if (threadIdx.x < o) {
            rs[threadIdx.x] += rs[threadIdx.x + o];
            rs2[threadIdx.x] += rs2[threadIdx.x + o];
        }
        __syncthreads();
    }
    const float mean = rs[0] / N;
    float var = rs2[0] / N - mean * mean;
    var = fmaxf(var, 0.f);
    const float rstd = rsqrtf(var + 1e-5f);

    for (int i = threadIdx.x * 4; i < N; i += 1024) {
        int c = g * 64 + (i >> 10);
        const float a = rstd * scale[c];
        const float bb2 = bias[c] - mean * a;
        float4 v = *(const float4*)(xp + i);
        float4 r = make_float4(v.x * a + bb2, v.y * a + bb2,
                               v.z * a + bb2, v.w * a + bb2);
        *(float4*)(g_h + base + i) = r;
    }
}

// ---------------------------------------------------------------------------
// QKV GEMM (NN): qkv[b,m,n] = sum_k W[m,k] * h[b,k,n] + bias[m]
// 128x128 tile, BK=8, 256 threads, 8x8 micro-tile, register prefetch.
// ---------------------------------------------------------------------------
__global__ void __launch_bounds__(256) qkv_gemm(const float* __restrict__ W,
                                                const float* __restrict__ bias) {
    __shared__ __align__(16) float As[8][128];
    __shared__ __align__(16) float Bs[8][128];
    const int b = blockIdx.z;
    const int n0 = blockIdx.x * 128;
    const int m0 = blockIdx.y * 128;
    const int tid = threadIdx.x;
    const int tx = tid & 15, ty = tid >> 4;

    const float* Bbase = g_h + (size_t)b * Cc * Ss;
    // A loader: thread -> (row m, 4 k's), transposed store
    const int a_m = tid >> 1;
    const int a_k = (tid & 1) * 4;
    // B loader: thread -> (k, 4 n's), direct store
    const int b_k = tid >> 5;
    const int b_n = (tid & 31) * 4;

    const float* Aptr = W + (size_t)(m0 + a_m) * Cc + a_k;
    const float* Bptr = Bbase + (size_t)b_k * Ss + n0 + b_n;

    float4 pa = *(const float4*)Aptr;
    float4 pb = *(const float4*)Bptr;

    float acc[8][8] = {};

    for (int k0 = 0; k0 < Cc; k0 += 8) {
        As[a_k + 0][a_m] = pa.x;
        As[a_k + 1][a_m] = pa.y;
        As[a_k + 2][a_m] = pa.z;
        As[a_k + 3][a_m] = pa.w;
        *(float4*)&Bs[b_k][b_n] = pb;
        __syncthreads();
        if (k0 + 8 < Cc) {
            pa = *(const float4*)(Aptr + k0 + 8);
            pb = *(const float4*)(Bptr + (size_t)(k0 + 8) * Ss);
        }
#pragma unroll
        for (int kk = 0; kk < 8; kk++) {
            float a8[8], b8[8];
            *(float4*)&a8[0] = *(const float4*)&As[kk][ty * 4];
            *(float4*)&a8[4] = *(const float4*)&As[kk][64 + ty * 4];
            *(float4*)&b8[0] = *(const float4*)&Bs[kk][tx * 4];
            *(float4*)&b8[4] = *(const float4*)&Bs[kk][64 + tx * 4];
#pragma unroll
            for (int i = 0; i < 8; i++)
#pragma unroll
                for (int j = 0; j < 8; j++)
                    acc[i][j] += a8[i] * b8[j];
        }
        __syncthreads();
    }

    float* out = g_qkv + (size_t)b * M3 * Ss;
#pragma unroll
    for (int i = 0; i < 8; i++) {
        const int m = m0 + (i < 4 ? ty * 4 + i : 64 + ty * 4 + i - 4);
        const float bv = bias[m];
#pragma unroll
        for (int gj = 0; gj < 2; gj++) {
            const int n = n0 + gj * 64 + tx * 4;
            float4 r = make_float4(acc[i][gj * 4 + 0] + bv, acc[i][gj * 4 + 1] + bv,
                                   acc[i][gj * 4 + 2] + bv, acc[i][gj * 4 + 3] + bv);
            *(float4*)(out + (size_t)m * Ss + n) = r;
        }
    }
}

// ---------------------------------------------------------------------------
// Attention (flash-style, fp32). One block per (b, head, s-tile of 128),
// t-tile of 64. 256 threads; score micro-tile 8 rows x 4 cols
// (rows ty*4+i and 64+ty*4+i, cols tx*4+j). O micro-tile same rows x d=tx*4.
// ---------------------------------------------------------------------------
__global__ void attn_kernel() {
    extern __shared__ float sm[];
    float* Qs = sm;                  // [64 d][128 s]
    float* Ks = Qs + 64 * 128;       // [64 d][64 t]
    float* Vst = Ks + 64 * 64;       // [64 t][68]  (t-major, padded)
    float* Ps = Vst + 64 * 68;       // [128 s][68] (s-major, padded)

    const int tid = threadIdx.x;
    const int tx = tid & 15, ty = tid >> 4;
    const int b = blockIdx.y >> 3;
    const int hh = blockIdx.y & 7;
    const int s0 = blockIdx.x * 128;

    const float* qk = g_qkv + (size_t)b * M3 * Ss;
    const float* Qg = qk + (size_t)(hh * HD) * Ss + s0;
    const float* Kg = qk + (size_t)(Cc + hh * HD) * Ss;
    const float* Vg = qk + (size_t)(2 * Cc + hh * HD) * Ss;

    // Load Q tile [64 d][128 s], pre-scaled by hd^-0.5 = 0.125
#pragma unroll
    for (int r = 0; r < 32; r++) {
        int idx = r * 256 + tid;
        int d = idx >> 7, ss = idx & 127;
        Qs[idx] = Qg[(size_t)d * Ss + ss] * 0.125f;
    }

    float m_i[8], l_i[8];
#pragma unroll
    for (int i = 0; i < 8; i++) { m_i[i] = -1e30f; l_i[i] = 0.f; }
    float accO[8][4] = {};

    int row[8];
#pragma unroll
    for (int i = 0; i < 8; i++)
        row[i] = (i < 4 ? ty * 4 + i : 64 + ty * 4 + i - 4);

    __syncthreads();

    for (int t0 = 0; t0 < Ss; t0 += 64) {
        // Load K tile [64 d][64 t] and V tile transposed [64 t][68]
#pragma unroll
        for (int r = 0; r < 16; r++) {
            int idx = r * 256 + tid;
            int d = idx >> 6, tt = idx & 63;
            Ks[idx] = Kg[(size_t)d * Ss + t0 + tt];
            Vst[tt * 68 + d] = Vg[(size_t)d * Ss + t0 + tt];
        }
        __syncthreads();

        // Score tile: sc[s][t] = sum_d Q[d][s]*K[d][t]
        float sc[8][4] = {};
#pragma unroll 8
        for (int kk = 0; kk < 64; kk++) {
            float a8[8], b4[4];
            *(float4*)&a8[0] = *(const float4*)&Qs[kk * 128 + ty * 4];
            *(float4*)&a8[4] = *(const float4*)&Qs[kk * 128 + 64 + ty * 4];
            *(float4*)b4 = *(const float4*)&Ks[kk * 64 + tx * 4];
#pragma unroll
            for (int i = 0; i < 8; i++)
#pragma unroll
                for (int j = 0; j < 4; j++)
                    sc[i][j] += a8[i] * b4[j];
        }

        // Online softmax per s-row; reduce across the 16 tx lanes (shfl<16
        // stays inside the half-warp owning this row group).
        float corr[8];
#pragma unroll
        for (int i = 0; i < 8; i++) {
            float tm = fmaxf(fmaxf(sc[i][0], sc[i][1]), fmaxf(sc[i][2], sc[i][3]));
#pragma unroll
            for (int off = 8; off >= 1; off >>= 1)
                tm = fmaxf(tm, __shfl_xor_sync(0xffffffffu, tm, off));
            const float nm = fmaxf(m_i[i], tm);
            corr[i] = __expf(m_i[i] - nm);
            float pv[4], ps = 0.f;
#pragma unroll
            for (int j = 0; j < 4; j++) { pv[j] = __expf(sc[i][j] - nm); ps += pv[j]; }
            *(float4*)&Ps[row[i] * 68 + tx * 4] =
                make_float4(pv[0], pv[1], pv[2], pv[3]);
#pragma unroll
            for (int off = 8; off >= 1; off >>= 1)
                ps += __shfl_xor_sync(0xffffffffu, ps, off);
            l_i[i] = l_i[i] * corr[i] + ps;
            m_i[i] = nm;
        }
        __syncthreads();

        // O accumulate: O[s][d] = O[s][d]*corr + sum_t P[s][t]*V[t][d]
#pragma unroll
        for (int i = 0; i < 8; i++)
#pragma unroll
            for (int j = 0; j < 4; j++) accO[i][j] *= corr[i];

        const int d4 = tx * 4;
#pragma unroll 2
        for (int kk = 0; kk < 64; kk += 4) {
            float4 v[4], p[8];
#pragma unroll
            for (int q = 0; q < 4; q++)
                v[q] = *(const float4*)&Vst[(kk + q) * 68 + d4];
#pragma unroll
            for (int i = 0; i < 8; i++)
                p[i] = *(const float4*)&Ps[row[i] * 68 + kk];
#pragma unroll
            for (int i = 0; i < 8; i++) {
                accO[i][0] += p[i].x * v[0].x + p[i].y * v[1].x + p[i].z * v[2].x + p[i].w * v[3].x;
                accO[i][1] += p[i].x * v[0].y + p[i].y * v[1].y + p[i].z * v[2].y + p[i].w * v[3].y;
                accO[i][2] += p[i].x * v[0].z + p[i].y * v[1].z + p[i].z * v[2].z + p[i].w * v[3].z;
                accO[i][3] += p[i].x * v[0].w + p[i].y * v[1].w + p[i].z * v[2].w + p[i].w * v[3].w;
            }
        }
        __syncthreads();
    }

    // Finalize: divide by l, write to hf[b*S+s][hh*64+d]
    float* out = g_hf + ((size_t)b * Ss + s0) * Cc + hh * HD;
#pragma unroll
    for (int i = 0; i < 8; i++) {
        const float inv = __fdividef(1.f, l_i[i]);
        float4 r = make_float4(accO[i][0] * inv, accO[i][1] * inv,
                               accO[i][2] * inv, accO[i][3] * inv);
        *(float4*)(out + (size_t)row[i] * Cc + tx * 4) = r;
    }
}

// ---------------------------------------------------------------------------
// INL step (NT GEMM + fused Euler/tanh epilogue):
// hout[r,o] = hin[r,o] + 0.1*tanh(sum_c hin[r,c]*W[o,c] + bias[o])
// 128x128 tile, BK=8, 8x8 micro-tile.
// ---------------------------------------------------------------------------
__global__ void __launch_bounds__(256) inl_gemm(int src, const float* __restrict__ W,
                                                const float* __restrict__ bias) {
    const float* hin = src ? g_hf2 : g_hf;
    float* hout = src ? g_hf : g_hf2;

    __shared__ __align__(16) float As[8][128];
    __shared__ __align__(16) float Ws[8][128];
    const int n0 = blockIdx.x * 128;
    const int m0 = blockIdx.y * 128;
    const int tid = threadIdx.x;
    const int tx = tid & 15, ty = tid >> 4;
    const int a_m = tid >> 1;
    const int a_k = (tid & 1) * 4;

    const float* Aptr = hin + (size_t)(m0 + a_m) * Cc + a_k;
    const float* Bptr = W + (size_t)(n0 + a_m) * Cc + a_k;

    float4 pa = *(const float4*)Aptr;
    float4 pb = *(const float4*)Bptr;

    float acc[8][8] = {};

    for (int k0 = 0; k0 < Cc; k0 += 8) {
        As[a_k + 0][a_m] = pa.x;
        As[a_k + 1][a_m] = pa.y;
        As[a_k + 2][a_m] = pa.z;
        As[a_k + 3][a_m] = pa.w;
        Ws[a_k + 0][a_m] = pb.x;
        Ws[a_k + 1][a_m] = pb.y;
        Ws[a_k + 2][a_m] = pb.z;
        Ws[a_k + 3][a_m] = pb.w;
        __syncthreads();
        if (k0 + 8 < Cc) {
            pa = *(const float4*)(Aptr + k0 + 8);
            pb = *(const float4*)(Bptr + k0 + 8);
        }
#pragma unroll
        for (int kk = 0; kk < 8; kk++) {
            float a8[8], b8[8];
            *(float4*)&a8[0] = *(const float4*)&As[kk][ty * 4];
            *(float4*)&a8[4] = *(const float4*)&As[kk][64 + ty * 4];
            *(float4*)&b8[0] = *(const float4*)&Ws[kk][tx * 4];
            *(float4*)&b8[4] = *(const float4*)&Ws[kk][64 + tx * 4];
#pragma unroll
            for (int i = 0; i < 8; i++)
#pragma unroll
                for (int j = 0; j < 8; j++)
                    acc[i][j] += a8[i] * b8[j];
        }
        __syncthreads();
    }

#pragma unroll
    for (int i = 0; i < 8; i++) {
        const size_t r = m0 + (i < 4 ? ty * 4 + i : 64 + ty * 4 + i - 4);
#pragma unroll
        for (int gj = 0; gj < 2; gj++) {
            const int c0 = n0 + gj * 64 + tx * 4;
            float4 prev = *(const float4*)(hin + r * Cc + c0);
            float4 o;
            o.x = prev.x + 0.1f * fast_tanh(acc[i][gj * 4 + 0] + bias[c0 + 0]);
            o.y = prev.y + 0.1f * fast_tanh(acc[i][gj * 4 + 1] + bias[c0 + 1]);
            o.z = prev.z + 0.1f * fast_tanh(acc[i][gj * 4 + 2] + bias[c0 + 2]);
            o.w = prev.w + 0.1f * fast_tanh(acc[i][gj * 4 + 3] + bias[c0 + 3]);
            *(float4*)(hout + r * Cc + c0) = o;
        }
    }
}

// ---------------------------------------------------------------------------
// Proj (NT GEMM + fused residual, transposed write):
// out[b,o,s] = x[b,o,s] + sum_c hf2[b*S+s,c]*W[o,c] + bias[o]
// ---------------------------------------------------------------------------
__global__ void __launch_bounds__(256) proj_gemm(const float* __restrict__ W,
                                                 const float* __restrict__ bias,
                                                 const float* __restrict__ x,
                                                 float* __restrict__ out) {
    const float* hin = g_hf2;

    __shared__ __align__(16) float As[8][128];
    __shared__ __align__(16) float Ws[8][128];
    const int n0 = blockIdx.x * 128;
    const int m0 = blockIdx.y * 128;
    const int tid = threadIdx.x;
    const int tx = tid & 15, ty = tid >> 4;
    const int a_m = tid >> 1;
    const int a_k = (tid & 1) * 4;

    const float* Aptr = hin + (size_t)(m0 + a_m) * Cc + a_k;
    const float* Bptr = W + (size_t)(n0 + a_m) * Cc + a_k;

    float4 pa = *(const float4*)Aptr;
    float4 pb = *(const float4*)Bptr;

    float acc[8][8] = {};

    for (int k0 = 0; k0 < Cc; k0 += 8) {
        As[a_k + 0][a_m] = pa.x;
        As[a_k + 1][a_m] = pa.y;
        As[a_k + 2][a_m] = pa.z;
        As[a_k + 3][a_m] = pa.w;
        Ws[a_k + 0][a_m] = pb.x;
        Ws[a_k + 1][a_m] = pb.y;
        Ws[a_k + 2][a_m] = pb.z;
        Ws[a_k + 3][a_m] = pb.w;
        __syncthreads();
        if (k0 + 8 < Cc) {
            pa = *(const float4*)(Aptr + k0 + 8);
            pb = *(const float4*)(Bptr + k0 + 8);
        }
#pragma unroll
        for (int kk = 0; kk < 8; kk++) {
            float a8[8], b8[8];
            *(float4*)&a8[0] = *(const float4*)&As[kk][ty * 4];
            *(float4*)&a8[4] = *(const float4*)&As[kk][64 + ty * 4];
            *(float4*)&b8[0] = *(const float4*)&Ws[kk][tx * 4];
            *(float4*)&b8[4] = *(const float4*)&Ws[kk][64 + tx * 4];
#pragma unroll
            for (int i = 0; i < 8; i++)
#pragma unroll
                for (int j = 0; j < 8; j++)
                    acc[i][j] += a8[i] * b8[j];
        }
        __syncthreads();
    }

    // Transposed epilogue: rows of this tile are (b, s); cols are o.
    const int b = m0 >> 10;   // 128 | 1024 so whole tile is one batch
#pragma unroll
    for (int gj = 0; gj < 2; gj++) {
#pragma unroll
        for (int j = 0; j < 4; j++) {
            const int o = n0 + gj * 64 + tx * 4 + j;
            const float bv = bias[o];
#pragma unroll
            for (int h = 0; h < 2; h++) {
                const int s_base = (m0 & 1023) + h * 64 + ty * 4;
                const size_t idx = ((size_t)b * Cc + o) * Ss + s_base;
                float4 xv = *(const float4*)(x + idx);
                float4 r = make_float4(xv.x + acc[h * 4 + 0][gj * 4 + j] + bv,
                                       xv.y + acc[h * 4 + 1][gj * 4 + j] + bv,
                                       xv.z + acc[h * 4 + 2][gj * 4 + j] + bv,
                                       xv.w + acc[h * 4 + 3][gj * 4 + j] + bv);
                *(float4*)(out + idx) = r;
            }
        }
    }
}

// ---------------------------------------------------------------------------
extern "C" void kernel_launch(void* const* d_in, const int* in_sizes, int n_in,
                              void* d_out, int out_size) {
    const float* x = (const float*)d_in[0];
    const float* gn_scale = (const float*)d_in[1];
    const float* gn_bias = (const float*)d_in[2];
    const float* qkv_w = (const float*)d_in[3];
    const float* qkv_b = (const float*)d_in[4];
    const float* proj_w = (const float*)d_in[5];
    const float* proj_b = (const float*)d_in[6];
    const float* inl_w = (const float*)d_in[7];
    const float* inl_b = (const float*)d_in[8];
    float* out = (float*)d_out;

    // 1. GroupNorm -> g_h
    gn_kernel<<<Bb * 8, 256>>>(x, gn_scale, gn_bias);

    // 2. QKV GEMM -> g_qkv
    qkv_gemm<<<dim3(Ss / 128, M3 / 128, Bb), 256>>>(qkv_w, qkv_b);

    // 3. Attention -> g_hf
    const int attn_smem =
        (64 * 128 + 64 * 64 + 64 * 68 + 128 * 68) * (int)sizeof(float);  // ~99 KB
    cudaFuncSetAttribute(attn_kernel,
                         cudaFuncAttributeMaxDynamicSharedMemorySize, attn_smem);
    attn_kernel<<<dim3(Ss / 128, Bb * NH), 256, attn_smem>>>();

    // 4. INL: 3 Euler steps (ping-pong g_hf <-> g_hf2), ends in g_hf2
    inl_gemm<<<dim3(Cc / 128, Bb * Ss / 128), 256>>>(0, inl_w, inl_b);
    inl_gemm<<<dim3(Cc / 128, Bb * Ss / 128), 256>>>(1, inl_w, inl_b);
    inl_gemm<<<dim3(Cc / 128, Bb * Ss / 128), 256>>>(0, inl_w, inl_b);

    // 5. Proj + residual -> d_out
    proj_gemm<<<dim3(Cc / 128, Bb * Ss / 128), 256>>>(proj_w, proj_b, x, out);
}